// round 15
// baseline (speedup 1.0000x reference)
#include <cuda_runtime.h>
#include <cstdint>

// out[b,c,h,w] = image[b,c,h,w] * weight[cam[b],c] + bias[cam[b],c]
// image: [16,3,1024,1024] f32; camera_index: [16] i32; weight/bias: [34,3] f32.
//
// FINAL roofline kernel (converged R8-R15, 8 reproductions). Evidence:
//   - all flat-grid geometries (TPB 256/512/1024, UNROLL 4/8): 6.05-6.17 TB/s,
//     ncu 56.3-57.5us typical — the mixed R+W HBM turnaround ceiling (~77% spec)
//   - persistent grid: regressed; __stwt stores: neutral
//   - occupancy 58-81% with 2x aggregate-MLP variation: zero throughput delta
//   - identical-source ncu variance up to ~8% (R12); wall stable 62.5-64.0us
//   - traffic irreducible: 201 MB read + 201 MB write, fp32 both ways
// Config: TPB=1024 (2 CTAs/SM, 64 warps), UNROLL=4 (MLP_p1=4), __ldcs/__stcs.
// Chunk = 4096 float4s; plane = 2^18 float4s, 2^18 % 4096 == 0 ->
// (b,c) uniform per block, scale/bias hoisted to one L1-hit lookup.

static constexpr int PLANE4  = 1 << 18;           // float4s per (b,c) plane
static constexpr int TOTAL4  = 16 * 3 * PLANE4;   // 12,582,912
static constexpr int TPB     = 1024;
static constexpr int UNROLL  = 4;
static constexpr int CHUNK   = TPB * UNROLL;      // 4096 float4s per block
static constexpr int NBLOCKS = TOTAL4 / CHUNK;    // 3072

__global__ void __launch_bounds__(TPB) colorcal_kernel(
        const float4* __restrict__ image,
        const int*    __restrict__ cam_idx,
        const float*  __restrict__ weight,
        const float*  __restrict__ bias,
        float4*       __restrict__ out) {
    int base = blockIdx.x * CHUNK;

    int plane = base >> 18;           // (b,c) uniform across the block
    int c = plane % 3;
    int b = plane / 3;
    int cam = __ldg(&cam_idx[b]);
    float s = __ldg(&weight[cam * 3 + c]);
    float t = __ldg(&bias[cam * 3 + c]);

    int i0 = base + threadIdx.x;

    // Front-batch 4 independent 16B loads (MLP_p1 = 4).
    float4 v[UNROLL];
#pragma unroll
    for (int k = 0; k < UNROLL; k++)
        v[k] = __ldcs(&image[i0 + k * TPB]);

#pragma unroll
    for (int k = 0; k < UNROLL; k++) {
        float4 r;
        r.x = fmaf(v[k].x, s, t);
        r.y = fmaf(v[k].y, s, t);
        r.z = fmaf(v[k].z, s, t);
        r.w = fmaf(v[k].w, s, t);
        __stcs(&out[i0 + k * TPB], r);
    }
}

extern "C" void kernel_launch(void* const* d_in, const int* in_sizes, int n_in,
                              void* d_out, int out_size) {
    const float4* image = (const float4*)d_in[0];
    const int*    cam   = (const int*)d_in[1];
    const float*  w     = (const float*)d_in[2];
    const float*  bse   = (const float*)d_in[3];
    float4*       out   = (float4*)d_out;

    colorcal_kernel<<<NBLOCKS, TPB>>>(image, cam, w, bse, out);
}

// round 16
// speedup vs baseline: 1.0081x; 1.0081x over previous
#include <cuda_runtime.h>
#include <cstdint>

// out[b,c,h,w] = image[b,c,h,w] * weight[cam[b],c] + bias[cam[b],c]
// image: [16,3,1024,1024] f32; camera_index: [16] i32; weight/bias: [34,3] f32.
//
// FINAL roofline kernel (converged R8-R16, 9 reproductions). Evidence:
//   - all flat-grid geometries (TPB 256/512/1024, UNROLL 4/8): 6.05-6.23 TB/s,
//     ncu 55.8-57.5us typical — the mixed R+W HBM turnaround ceiling (~78% spec)
//   - persistent grid: regressed; __stwt stores: neutral
//   - occupancy 58-81% with 2x aggregate-MLP variation: zero throughput delta
//   - identical-source ncu variance ±5% at natural clocks; wall ±1.2%
//   - traffic irreducible: 201 MB read + 201 MB write, fp32 both ways
// Config: TPB=1024 (2 CTAs/SM, 64 warps), UNROLL=4 (MLP_p1=4), __ldcs/__stcs.
// Chunk = 4096 float4s; plane = 2^18 float4s, 2^18 % 4096 == 0 ->
// (b,c) uniform per block, scale/bias hoisted to one L1-hit lookup.

static constexpr int PLANE4  = 1 << 18;           // float4s per (b,c) plane
static constexpr int TOTAL4  = 16 * 3 * PLANE4;   // 12,582,912
static constexpr int TPB     = 1024;
static constexpr int UNROLL  = 4;
static constexpr int CHUNK   = TPB * UNROLL;      // 4096 float4s per block
static constexpr int NBLOCKS = TOTAL4 / CHUNK;    // 3072

__global__ void __launch_bounds__(TPB) colorcal_kernel(
        const float4* __restrict__ image,
        const int*    __restrict__ cam_idx,
        const float*  __restrict__ weight,
        const float*  __restrict__ bias,
        float4*       __restrict__ out) {
    int base = blockIdx.x * CHUNK;

    int plane = base >> 18;           // (b,c) uniform across the block
    int c = plane % 3;
    int b = plane / 3;
    int cam = __ldg(&cam_idx[b]);
    float s = __ldg(&weight[cam * 3 + c]);
    float t = __ldg(&bias[cam * 3 + c]);

    int i0 = base + threadIdx.x;

    // Front-batch 4 independent 16B loads (MLP_p1 = 4).
    float4 v[UNROLL];
#pragma unroll
    for (int k = 0; k < UNROLL; k++)
        v[k] = __ldcs(&image[i0 + k * TPB]);

#pragma unroll
    for (int k = 0; k < UNROLL; k++) {
        float4 r;
        r.x = fmaf(v[k].x, s, t);
        r.y = fmaf(v[k].y, s, t);
        r.z = fmaf(v[k].z, s, t);
        r.w = fmaf(v[k].w, s, t);
        __stcs(&out[i0 + k * TPB], r);
    }
}

extern "C" void kernel_launch(void* const* d_in, const int* in_sizes, int n_in,
                              void* d_out, int out_size) {
    const float4* image = (const float4*)d_in[0];
    const int*    cam   = (const int*)d_in[1];
    const float*  w     = (const float*)d_in[2];
    const float*  bse   = (const float*)d_in[3];
    float4*       out   = (float4*)d_out;

    colorcal_kernel<<<NBLOCKS, TPB>>>(image, cam, w, bse, out);
}

// round 17
// speedup vs baseline: 1.0284x; 1.0201x over previous
#include <cuda_runtime.h>
#include <cstdint>

// out[b,c,h,w] = image[b,c,h,w] * weight[cam[b],c] + bias[cam[b],c]
// image: [16,3,1024,1024] f32; camera_index: [16] i32; weight/bias: [34,3] f32.
//
// FINAL roofline kernel (converged R8-R17, 10 reproductions). Evidence:
//   - all flat-grid geometries (TPB 256/512/1024, UNROLL 4/8): 6.05-6.23 TB/s,
//     ncu 55.8-57.5us — the mixed R+W HBM turnaround ceiling (~77-78% of spec)
//   - persistent grid: regressed; __stwt stores: neutral
//   - occupancy 58-81% with 2x aggregate-MLP variation: zero throughput delta
//   - identical-source ncu variance ±5% at natural clocks; wall ±1.2%
//   - traffic irreducible: 201 MB read + 201 MB write, fp32 both ways
// Config: TPB=1024 (2 CTAs/SM, 64 warps), UNROLL=4 (MLP_p1=4), __ldcs/__stcs.
// Chunk = 4096 float4s; plane = 2^18 float4s, 2^18 % 4096 == 0 ->
// (b,c) uniform per block, scale/bias hoisted to one L1-hit lookup.

static constexpr int PLANE4  = 1 << 18;           // float4s per (b,c) plane
static constexpr int TOTAL4  = 16 * 3 * PLANE4;   // 12,582,912
static constexpr int TPB     = 1024;
static constexpr int UNROLL  = 4;
static constexpr int CHUNK   = TPB * UNROLL;      // 4096 float4s per block
static constexpr int NBLOCKS = TOTAL4 / CHUNK;    // 3072

__global__ void __launch_bounds__(TPB) colorcal_kernel(
        const float4* __restrict__ image,
        const int*    __restrict__ cam_idx,
        const float*  __restrict__ weight,
        const float*  __restrict__ bias,
        float4*       __restrict__ out) {
    int base = blockIdx.x * CHUNK;

    int plane = base >> 18;           // (b,c) uniform across the block
    int c = plane % 3;
    int b = plane / 3;
    int cam = __ldg(&cam_idx[b]);
    float s = __ldg(&weight[cam * 3 + c]);
    float t = __ldg(&bias[cam * 3 + c]);

    int i0 = base + threadIdx.x;

    // Front-batch 4 independent 16B loads (MLP_p1 = 4).
    float4 v[UNROLL];
#pragma unroll
    for (int k = 0; k < UNROLL; k++)
        v[k] = __ldcs(&image[i0 + k * TPB]);

#pragma unroll
    for (int k = 0; k < UNROLL; k++) {
        float4 r;
        r.x = fmaf(v[k].x, s, t);
        r.y = fmaf(v[k].y, s, t);
        r.z = fmaf(v[k].z, s, t);
        r.w = fmaf(v[k].w, s, t);
        __stcs(&out[i0 + k * TPB], r);
    }
}

extern "C" void kernel_launch(void* const* d_in, const int* in_sizes, int n_in,
                              void* d_out, int out_size) {
    const float4* image = (const float4*)d_in[0];
    const int*    cam   = (const int*)d_in[1];
    const float*  w     = (const float*)d_in[2];
    const float*  bse   = (const float*)d_in[3];
    float4*       out   = (float4*)d_out;

    colorcal_kernel<<<NBLOCKS, TPB>>>(image, cam, w, bse, out);
}